// round 4
// baseline (speedup 1.0000x reference)
#include <cuda_runtime.h>
#include <math.h>

#define N   384
#define NN  (384*384)

// ---- scratch (device globals; no allocation allowed) ----
__device__ float g_q   [256*N];
__device__ float g_Kn  [256*N];
__device__ float g_Vn  [256*N];
__device__ float g_nf  [256*N];
__device__ float g_hEo [64*N];
__device__ float g_mask[N];

// ---- packed f32x2 helpers (Blackwell FFMA2) ----
__device__ __forceinline__ unsigned long long pk2(float a, float b) {
    unsigned long long d;
    asm("mov.b64 %0, {%1, %2};" : "=l"(d) : "f"(a), "f"(b));
    return d;
}
__device__ __forceinline__ unsigned long long fma2(unsigned long long a,
                                                   unsigned long long b,
                                                   unsigned long long c) {
    unsigned long long d;
    asm("fma.rn.f32x2 %0, %1, %2, %3;" : "=l"(d) : "l"(a), "l"(b), "l"(c));
    return d;
}
__device__ __forceinline__ float2 upk(unsigned long long v) {
    float2 r;
    asm("mov.b64 {%0, %1}, %2;" : "=f"(r.x), "=f"(r.y) : "l"(v));
    return r;
}
union F4U { float4 f; unsigned long long u[2]; };

// ============================================================
// Kernel 1: fused GEMM q|Kn|Vn. M=768, K=128, cols=384.
// grid(24,12), 256 thr, tile 32x32. Block(0,0) also decodes mask.
// ============================================================
__global__ __launch_bounds__(256) void k_prep(
    const float* __restrict__ nodes,
    const float* __restrict__ Wq,
    const float* __restrict__ Wk,
    const float* __restrict__ Wv,
    const unsigned int* __restrict__ maskw)
{
    __shared__ float Ws[32][33];
    __shared__ float Ns[32][36];
    __shared__ int s_mode;
    int tid = threadIdx.x;

    if (blockIdx.x == 0 && blockIdx.y == 0) {
        if (tid == 0) {
            int md = 0;
            for (int w = 0; w < 96; w++) {
                unsigned v = maskw[w];
                if (v == 0x3f800000u) { md = 0; break; }   // float32
                if (v > 1u)           { md = 2; break; }   // packed u8
            }
            s_mode = md;
        }
        __syncthreads();
        int mode = s_mode;
        for (int j = tid; j < N; j += 256) {
            float val;
            if (mode == 2) {
                unsigned w = maskw[j >> 2];
                val = ((w >> ((j & 3) * 8)) & 0xffu) ? 1.0f : 0.0f;
            } else {
                val = maskw[j] ? 1.0f : 0.0f;   // int32 or f32 bits
            }
            g_mask[j] = val;
        }
    }

    int r0 = blockIdx.x * 32, n0 = blockIdx.y * 32;
    int co = tid & 31, ro = (tid >> 5) * 4;
    float acc[4] = {0.f, 0.f, 0.f, 0.f};

    for (int k0 = 0; k0 < 128; k0 += 32) {
        {
            int rr = tid >> 3, kl = (tid & 7) * 4;
            int r = r0 + rr;
            const float* wp;
            if      (r < 256) wp = Wq + r * 128;
            else if (r < 512) wp = Wk + (r - 256) * 192;
            else              wp = Wv + (r - 512) * 192;
            float4 w = *(const float4*)(wp + k0 + kl);
            Ws[rr][kl+0] = w.x; Ws[rr][kl+1] = w.y;
            Ws[rr][kl+2] = w.z; Ws[rr][kl+3] = w.w;
        }
        {
            int kk = tid >> 3, cl = (tid & 7) * 4;
            float4 v = *(const float4*)(nodes + (k0 + kk) * N + n0 + cl);
            Ns[kk][cl+0] = v.x; Ns[kk][cl+1] = v.y;
            Ns[kk][cl+2] = v.z; Ns[kk][cl+3] = v.w;
        }
        __syncthreads();
        #pragma unroll
        for (int k = 0; k < 32; k++) {
            float ev = Ns[k][co];
            acc[0] = fmaf(Ws[ro+0][k], ev, acc[0]);
            acc[1] = fmaf(Ws[ro+1][k], ev, acc[1]);
            acc[2] = fmaf(Ws[ro+2][k], ev, acc[2]);
            acc[3] = fmaf(Ws[ro+3][k], ev, acc[3]);
        }
        __syncthreads();
    }
    #pragma unroll
    for (int q = 0; q < 4; q++) {
        int r = r0 + ro + q;
        float* op;
        if      (r < 256) op = g_q  + r * N;
        else if (r < 512) op = g_Kn + (r - 256) * N;
        else              op = g_Vn + (r - 512) * N;
        op[n0 + co] = acc[q];
    }
}

// ============================================================
// Kernel 2: fused attention row, single pass over edges,
// masked-j compaction. grid(384), 384 thr, ~125KB dyn smem.
// ============================================================
#define ES_STRIDE 388
#define ATTN_FLOATS (64*ES_STRIDE + 384*12 + 3*256 + 512 + 512 + 8 + 384 + 384 + 4)
#define ATTN_SMEM (ATTN_FLOATS * 4)

__global__ __launch_bounds__(384) void k_attn(
    const float* __restrict__ edges,
    const float* __restrict__ Wk,
    const float* __restrict__ Wv)
{
    extern __shared__ float sm[];
    float* Es    = sm;                     // [64][388]
    float* s_p   = Es + 64 * ES_STRIDE;    // [384][12]
    float* s_qi  = s_p + 384 * 12;         // 256
    float* s_Kni = s_qi + 256;
    float* s_Vni = s_Kni + 256;
    float* s_Qk  = s_Vni + 256;            // [64][8]
    float* s_T   = s_Qk + 512;             // [8][64]
    float* s_sb  = s_T + 512;              // 8
    float* s_mf  = s_sb + 8;               // 384
    int*   s_jl  = (int*)(s_mf + 384);     // 384 valid-j list
    int*   s_cnt = s_jl + 384;

    int i = blockIdx.x;
    int tid = threadIdx.x, lane = tid & 31, wid = tid >> 5;

    if (tid == 0) *s_cnt = 0;
    if (tid < 256) {
        s_qi [tid] = g_q [tid * N + i];
        s_Kni[tid] = g_Kn[tid * N + i];
        s_Vni[tid] = g_Vn[tid * N + i];
    }
    s_mf[tid] = g_mask[tid];

    // stage edges[0..63, i, 0..383] into smem (coalesced float4)
    const float* erow = edges + (size_t)i * N;
    for (int idx = tid; idx < 64 * 96; idx += 384) {
        int e = idx / 96, j4 = idx - e * 96;
        float4 v = *(const float4*)(erow + (size_t)e * NN + j4 * 4);
        *(float4*)&Es[e * ES_STRIDE + j4 * 4] = v;
    }
    __syncthreads();

    // compacted valid-j list
    if (s_mf[tid] > 0.f) {
        int k = atomicAdd(s_cnt, 1);
        s_jl[k] = tid;
    }

    const float rs = 0.17677669529663687f;  // 1/sqrt(32)

    // Qk[e][h] = rs * sum_a q[h*32+a] * Wk[h*32+a][128+e]  (512 items)
    {
        int idx = tid;
        #pragma unroll
        for (int rep = 0; rep < 2; rep++) {
            if (idx < 512) {
                int h = idx >> 6, e = idx & 63;
                const float* wkp = Wk + (h * 32) * 192 + 128 + e;
                float acc = 0.f;
                #pragma unroll
                for (int a = 0; a < 32; a++) acc = fmaf(s_qi[h * 32 + a], wkp[a * 192], acc);
                s_Qk[e * 8 + h] = acc * rs;
            }
            idx += 384;
        }
    }
    if (tid < 256) {   // sim_base[h], warps 0..7
        float v = s_qi[tid] * s_Kni[tid];
        #pragma unroll
        for (int o = 16; o; o >>= 1) v += __shfl_xor_sync(0xffffffffu, v, o);
        if (lane == 0) s_sb[wid] = v * rs;
    }
    __syncthreads();

    int cnt = *s_cnt;

    // pass 1: sim for valid j only. thread = (j-slot, h-half of 4)
    {
        int hh = tid & 1;                       // 0 -> h0..3, 1 -> h4..7
        F4U sb; sb.f = *(const float4*)&s_sb[hh * 4];
        for (int idx = tid >> 1; idx < cnt; idx += 192) {
            int j = s_jl[idx];
            unsigned long long acc2[2] = { sb.u[0], sb.u[1] };
            const float* ep = Es + j;
            const float* qp = s_Qk + hh * 4;
            #pragma unroll 8
            for (int e = 0; e < 64; e++) {
                float ev = ep[e * ES_STRIDE];
                unsigned long long evd = pk2(ev, ev);
                F4U q; q.f = *(const float4*)(qp + e * 8);
                acc2[0] = fma2(q.u[0], evd, acc2[0]);
                acc2[1] = fma2(q.u[1], evd, acc2[1]);
            }
            F4U o;
            float2 a = upk(acc2[0]), b = upk(acc2[1]);
            o.f = make_float4(a.x, a.y, b.x, b.y);
            *(float4*)&s_p[j * 12 + hh * 4] = o.f;
        }
    }
    __syncthreads();

    float maski = s_mf[i];

    // masked softmax over valid j: warp h (h<8) owns head h
    if (wid < 8) {
        int h = wid;
        float m = -INFINITY;
        for (int idx = lane; idx < cnt; idx += 32) m = fmaxf(m, s_p[s_jl[idx] * 12 + h]);
        #pragma unroll
        for (int o = 16; o; o >>= 1) m = fmaxf(m, __shfl_xor_sync(0xffffffffu, m, o));
        float sum = 0.f;
        for (int idx = lane; idx < cnt; idx += 32) {
            int j = s_jl[idx];
            float ev = __expf(s_p[j * 12 + h] - m);
            s_p[j * 12 + h] = ev;
            sum += ev;
        }
        #pragma unroll
        for (int o = 16; o; o >>= 1) sum += __shfl_xor_sync(0xffffffffu, sum, o);
        float inv = maski / sum;
        for (int idx = lane; idx < cnt; idx += 32) s_p[s_jl[idx] * 12 + h] *= inv;
    }
    __syncthreads();

    // pass 2: T[h][e] = sum over valid j of p[h][j]*E[e][j]; 12 warps over e
    for (int e = wid; e < 64; e += 12) {
        const float* ep = Es + e * ES_STRIDE;
        unsigned long long acc2[4] = {0ull, 0ull, 0ull, 0ull};
        for (int idx = lane; idx < cnt; idx += 32) {
            int j = s_jl[idx];
            float ev = ep[j];
            unsigned long long evd = pk2(ev, ev);
            F4U p0; p0.f = *(const float4*)&s_p[j * 12];
            F4U p1; p1.f = *(const float4*)&s_p[j * 12 + 4];
            acc2[0] = fma2(p0.u[0], evd, acc2[0]);
            acc2[1] = fma2(p0.u[1], evd, acc2[1]);
            acc2[2] = fma2(p1.u[0], evd, acc2[2]);
            acc2[3] = fma2(p1.u[1], evd, acc2[3]);
        }
        #pragma unroll
        for (int hp = 0; hp < 4; hp++) {
            float2 v = upk(acc2[hp]);
            #pragma unroll
            for (int o = 16; o; o >>= 1) {
                v.x += __shfl_xor_sync(0xffffffffu, v.x, o);
                v.y += __shfl_xor_sync(0xffffffffu, v.y, o);
            }
            if (lane == 0) {
                s_T[(2 * hp)     * 64 + e] = v.x;
                s_T[(2 * hp + 1) * 64 + e] = v.y;
            }
        }
    }
    __syncthreads();

    // node_features[hv,i]
    if (tid < 256) {
        int hv = tid, h = hv >> 5;
        const float* wvp = Wv + hv * 192 + 128;
        float acc = s_Vni[hv] * maski;
        #pragma unroll
        for (int e = 0; e < 64; e++) acc = fmaf(wvp[e], s_T[h * 64 + e], acc);
        g_nf[hv * N + i] = acc;
    }
}

// ============================================================
// Kernel 3: node_out = Wo@nf ; hEo = 0.5*We[:,:256]@nf
// M=192, K=256, cols=384. grid(6,12), 256 thr, tile 32x32.
// ============================================================
__global__ __launch_bounds__(256) void k_post(
    const float* __restrict__ Wo,
    const float* __restrict__ We,
    float* __restrict__ out)
{
    __shared__ float Ws[32][33];
    __shared__ float Ns[32][36];
    int tid = threadIdx.x;
    int r0 = blockIdx.x * 32, n0 = blockIdx.y * 32;
    int co = tid & 31, ro = (tid >> 5) * 4;
    float acc[4] = {0.f, 0.f, 0.f, 0.f};

    for (int k0 = 0; k0 < 256; k0 += 32) {
        {
            int rr = tid >> 3, kl = (tid & 7) * 4;
            int r = r0 + rr;
            const float* wp = (r < 128) ? (Wo + r * 256) : (We + (r - 128) * 320);
            float4 w = *(const float4*)(wp + k0 + kl);
            Ws[rr][kl+0] = w.x; Ws[rr][kl+1] = w.y;
            Ws[rr][kl+2] = w.z; Ws[rr][kl+3] = w.w;
        }
        {
            int kk = tid >> 3, cl = (tid & 7) * 4;
            float4 v = *(const float4*)(g_nf + (k0 + kk) * N + n0 + cl);
            Ns[kk][cl+0] = v.x; Ns[kk][cl+1] = v.y;
            Ns[kk][cl+2] = v.z; Ns[kk][cl+3] = v.w;
        }
        __syncthreads();
        #pragma unroll
        for (int k = 0; k < 32; k++) {
            float ev = Ns[k][co];
            acc[0] = fmaf(Ws[ro+0][k], ev, acc[0]);
            acc[1] = fmaf(Ws[ro+1][k], ev, acc[1]);
            acc[2] = fmaf(Ws[ro+2][k], ev, acc[2]);
            acc[3] = fmaf(Ws[ro+3][k], ev, acc[3]);
        }
        __syncthreads();
    }
    #pragma unroll
    for (int q = 0; q < 4; q++) {
        int r = r0 + ro + q;
        if (r < 128) out[r * N + n0 + co] = acc[q];
        else         g_hEo[(r - 128) * N + n0 + co] = 0.5f * acc[q];
    }
}

// ============================================================
// Kernel 4: edge_out. GEMM [64o,64e] x [64e, 147456c] + rank-1 adds.
// grid(288), 256 thr. CTA tile 64o x 512c. Thread tile 8o x 16c
// (two 8-wide strips). FFMA2 packed along c-pairs.
// ============================================================
#define EG_ST 516
#define EDGE_SMEM ((64*72 + 64*EG_ST) * 4)

__global__ __launch_bounds__(256, 1) void k_edge(
    const float* __restrict__ edges,
    const float* __restrict__ We,
    float* __restrict__ out)
{
    extern __shared__ float esm[];
    float* Ws = esm;              // [64][72]  Ws[e][o]
    float* Es = esm + 64 * 72;    // [64][516]

    int tid = threadIdx.x, lane = tid & 31, wid = tid >> 5;
    size_t cbase = (size_t)blockIdx.x * 512;

    // load We_edge transposed
    {
        int o = tid >> 2, e0 = (tid & 3) * 16;
        const float* wp = We + o * 320 + 256 + e0;
        #pragma unroll
        for (int u = 0; u < 16; u += 4) {
            float4 w = *(const float4*)(wp + u);
            Ws[(e0+u+0)*72 + o] = w.x; Ws[(e0+u+1)*72 + o] = w.y;
            Ws[(e0+u+2)*72 + o] = w.z; Ws[(e0+u+3)*72 + o] = w.w;
        }
    }
    // stage Es: 64 e x 512 c
    #pragma unroll
    for (int it = 0; it < 32; it++) {
        int idx = it * 256 + tid;
        int e = idx >> 7, c4 = idx & 127;
        float4 v = *(const float4*)(edges + (size_t)e * NN + cbase + c4 * 4);
        *(float4*)&Es[e * EG_ST + c4 * 4] = v;
    }
    __syncthreads();

    int o0 = wid * 8;

    unsigned long long acc2[8][8];
    #pragma unroll
    for (int o = 0; o < 8; o++)
        #pragma unroll
        for (int p = 0; p < 8; p++) acc2[o][p] = 0ull;

    #pragma unroll 2
    for (int e = 0; e < 64; e++) {
        const float* wr = Ws + e * 72 + o0;
        float4 wA = *(const float4*)wr;
        float4 wB = *(const float4*)(wr + 4);
        unsigned long long wd[8];
        wd[0] = pk2(wA.x, wA.x); wd[1] = pk2(wA.y, wA.y);
        wd[2] = pk2(wA.z, wA.z); wd[3] = pk2(wA.w, wA.w);
        wd[4] = pk2(wB.x, wB.x); wd[5] = pk2(wB.y, wB.y);
        wd[6] = pk2(wB.z, wB.z); wd[7] = pk2(wB.w, wB.w);
        const float* er = Es + e * EG_ST + lane * 8;
        F4U e0a, e0b, e1a, e1b;
        e0a.f = *(const float4*)er;
        e0b.f = *(const float4*)(er + 4);
        e1a.f = *(const float4*)(er + 256);
        e1b.f = *(const float4*)(er + 260);
        unsigned long long ev[8] = { e0a.u[0], e0a.u[1], e0b.u[0], e0b.u[1],
                                     e1a.u[0], e1a.u[1], e1b.u[0], e1b.u[1] };
        #pragma unroll
        for (int o = 0; o < 8; o++)
            #pragma unroll
            for (int p = 0; p < 8; p++)
                acc2[o][p] = fma2(wd[o], ev[p], acc2[o][p]);
    }

    // epilogue: add hEo[o,i] + hEo[o,j], store
    float* ob = out + 128 * N;
    size_t c0 = cbase + lane * 8;
    #pragma unroll
    for (int s = 0; s < 2; s++) {
        size_t c = c0 + s * 256;
        int ii = (int)(c / 384), jj = (int)(c % 384);
        #pragma unroll
        for (int o = 0; o < 8; o++) {
            int oo = o0 + o;
            float eoi = g_hEo[oo * N + ii];
            float4 ej0 = *(const float4*)(g_hEo + oo * N + jj);
            float4 ej1 = *(const float4*)(g_hEo + oo * N + jj + 4);
            float2 v0 = upk(acc2[o][s*4+0]);
            float2 v1 = upk(acc2[o][s*4+1]);
            float2 v2 = upk(acc2[o][s*4+2]);
            float2 v3 = upk(acc2[o][s*4+3]);
            float* op = ob + (size_t)oo * NN + c;
            *(float4*)op       = make_float4(v0.x + eoi + ej0.x, v0.y + eoi + ej0.y,
                                             v1.x + eoi + ej0.z, v1.y + eoi + ej0.w);
            *(float4*)(op + 4) = make_float4(v2.x + eoi + ej1.x, v2.y + eoi + ej1.y,
                                             v3.x + eoi + ej1.z, v3.y + eoi + ej1.w);
        }
    }
}

// ============================================================
extern "C" void kernel_launch(void* const* d_in, const int* in_sizes, int n_in,
                              void* d_out, int out_size)
{
    const float* nodes = (const float*)d_in[0];
    const float* edges = (const float*)d_in[1];
    const unsigned int* mask = (const unsigned int*)d_in[2];
    const float* Wq = (const float*)d_in[3];
    const float* Wk = (const float*)d_in[4];
    const float* Wv = (const float*)d_in[5];
    const float* Wo = (const float*)d_in[6];
    const float* We = (const float*)d_in[7];
    float* out = (float*)d_out;

    cudaFuncSetAttribute(k_attn, cudaFuncAttributeMaxDynamicSharedMemorySize, ATTN_SMEM);
    cudaFuncSetAttribute(k_edge, cudaFuncAttributeMaxDynamicSharedMemorySize, EDGE_SMEM);

    k_prep<<<dim3(24, 12), 256>>>(nodes, Wq, Wk, Wv, mask);
    k_attn<<<384, 384, ATTN_SMEM>>>(edges, Wk, Wv);
    k_post<<<dim3(6, 12), 256>>>(Wo, We, out);
    k_edge<<<288, 256, EDGE_SMEM>>>(edges, We, out);
}

// round 5
// speedup vs baseline: 1.0722x; 1.0722x over previous
#include <cuda_runtime.h>
#include <math.h>

#define N   384
#define NN  (384*384)

// ---- scratch (device globals; no allocation allowed) ----
__device__ float g_q   [256*N];
__device__ float g_Kn  [256*N];
__device__ float g_Vn  [256*N];
__device__ float g_nf  [256*N];
__device__ float g_hEo [64*N];
__device__ float g_mask[N];

// ---- packed f32x2 helpers (Blackwell FFMA2) ----
__device__ __forceinline__ unsigned long long pk2(float a, float b) {
    unsigned long long d;
    asm("mov.b64 %0, {%1, %2};" : "=l"(d) : "f"(a), "f"(b));
    return d;
}
__device__ __forceinline__ unsigned long long fma2(unsigned long long a,
                                                   unsigned long long b,
                                                   unsigned long long c) {
    unsigned long long d;
    asm("fma.rn.f32x2 %0, %1, %2, %3;" : "=l"(d) : "l"(a), "l"(b), "l"(c));
    return d;
}
__device__ __forceinline__ float2 upk(unsigned long long v) {
    float2 r;
    asm("mov.b64 {%0, %1}, %2;" : "=f"(r.x), "=f"(r.y) : "l"(v));
    return r;
}
union F4U { float4 f; unsigned long long u[2]; };

// ============================================================
// Kernel 1: fused GEMM q|Kn|Vn. M=768, K=128, cols=384.
// grid(24,12), 256 thr, tile 32x32. Block(0,0) decodes mask
// with PARALLEL mode detection (no serial LDG chain).
// ============================================================
__global__ __launch_bounds__(256) void k_prep(
    const float* __restrict__ nodes,
    const float* __restrict__ Wq,
    const float* __restrict__ Wk,
    const float* __restrict__ Wv,
    const unsigned int* __restrict__ maskw)
{
    __shared__ float Ws[32][33];
    __shared__ float Ns[32][36];
    __shared__ int s_flagF, s_flagB;
    int tid = threadIdx.x;

    if (blockIdx.x == 0 && blockIdx.y == 0) {
        if (tid == 0) { s_flagF = 0; s_flagB = 0; }
        __syncthreads();
        unsigned v = 0;
        if (tid < 96) {
            v = maskw[tid];
            if (v == 0x3f800000u)      atomicOr(&s_flagF, 1);  // float32 1.0
            else if (v > 1u)           atomicOr(&s_flagB, 1);  // packed u8
        }
        __syncthreads();
        bool byte_mode = (!s_flagF) && s_flagB;
        for (int j = tid; j < N; j += 256) {
            float val;
            if (byte_mode) {
                unsigned w = maskw[j >> 2];
                val = ((w >> ((j & 3) * 8)) & 0xffu) ? 1.0f : 0.0f;
            } else {
                val = maskw[j] ? 1.0f : 0.0f;   // int32 or f32 bits
            }
            g_mask[j] = val;
        }
    }

    int r0 = blockIdx.x * 32, n0 = blockIdx.y * 32;
    int co = tid & 31, ro = (tid >> 5) * 4;
    float acc[4] = {0.f, 0.f, 0.f, 0.f};

    for (int k0 = 0; k0 < 128; k0 += 32) {
        {
            int rr = tid >> 3, kl = (tid & 7) * 4;
            int r = r0 + rr;
            const float* wp;
            if      (r < 256) wp = Wq + r * 128;
            else if (r < 512) wp = Wk + (r - 256) * 192;
            else              wp = Wv + (r - 512) * 192;
            float4 w = *(const float4*)(wp + k0 + kl);
            Ws[rr][kl+0] = w.x; Ws[rr][kl+1] = w.y;
            Ws[rr][kl+2] = w.z; Ws[rr][kl+3] = w.w;
        }
        {
            int kk = tid >> 3, cl = (tid & 7) * 4;
            float4 v = *(const float4*)(nodes + (k0 + kk) * N + n0 + cl);
            Ns[kk][cl+0] = v.x; Ns[kk][cl+1] = v.y;
            Ns[kk][cl+2] = v.z; Ns[kk][cl+3] = v.w;
        }
        __syncthreads();
        #pragma unroll
        for (int k = 0; k < 32; k++) {
            float ev = Ns[k][co];
            acc[0] = fmaf(Ws[ro+0][k], ev, acc[0]);
            acc[1] = fmaf(Ws[ro+1][k], ev, acc[1]);
            acc[2] = fmaf(Ws[ro+2][k], ev, acc[2]);
            acc[3] = fmaf(Ws[ro+3][k], ev, acc[3]);
        }
        __syncthreads();
    }
    #pragma unroll
    for (int q = 0; q < 4; q++) {
        int r = r0 + ro + q;
        float* op;
        if      (r < 256) op = g_q  + r * N;
        else if (r < 512) op = g_Kn + (r - 256) * N;
        else              op = g_Vn + (r - 512) * N;
        op[n0 + co] = acc[q];
    }
}

// ============================================================
// Kernel 2: fused attention row, single pass over edges,
// masked-j compaction. grid(384), 384 thr, ~125KB dyn smem.
// ============================================================
#define ES_STRIDE 388
#define ATTN_FLOATS (64*ES_STRIDE + 384*12 + 3*256 + 512 + 512 + 8 + 384 + 384 + 4)
#define ATTN_SMEM (ATTN_FLOATS * 4)

__global__ __launch_bounds__(384) void k_attn(
    const float* __restrict__ edges,
    const float* __restrict__ Wk,
    const float* __restrict__ Wv)
{
    extern __shared__ float sm[];
    float* Es    = sm;                     // [64][388]
    float* s_p   = Es + 64 * ES_STRIDE;    // [384][12]
    float* s_qi  = s_p + 384 * 12;         // 256
    float* s_Kni = s_qi + 256;
    float* s_Vni = s_Kni + 256;
    float* s_Qk  = s_Vni + 256;            // [64][8]
    float* s_T   = s_Qk + 512;             // [8][64]
    float* s_sb  = s_T + 512;              // 8
    float* s_mf  = s_sb + 8;               // 384
    int*   s_jl  = (int*)(s_mf + 384);     // 384 valid-j list
    int*   s_cnt = s_jl + 384;

    int i = blockIdx.x;
    int tid = threadIdx.x, lane = tid & 31, wid = tid >> 5;

    if (tid == 0) *s_cnt = 0;
    if (tid < 256) {
        s_qi [tid] = g_q [tid * N + i];
        s_Kni[tid] = g_Kn[tid * N + i];
        s_Vni[tid] = g_Vn[tid * N + i];
    }
    s_mf[tid] = g_mask[tid];

    // stage edges[0..63, i, 0..383] into smem (coalesced float4)
    const float* erow = edges + (size_t)i * N;
    for (int idx = tid; idx < 64 * 96; idx += 384) {
        int e = idx / 96, j4 = idx - e * 96;
        float4 v = *(const float4*)(erow + (size_t)e * NN + j4 * 4);
        *(float4*)&Es[e * ES_STRIDE + j4 * 4] = v;
    }
    __syncthreads();

    // compacted valid-j list
    if (s_mf[tid] > 0.f) {
        int k = atomicAdd(s_cnt, 1);
        s_jl[k] = tid;
    }

    const float rs = 0.17677669529663687f;  // 1/sqrt(32)

    // Qk[e][h] = rs * sum_a q[h*32+a] * Wk[h*32+a][128+e]  (512 items)
    {
        int idx = tid;
        #pragma unroll
        for (int rep = 0; rep < 2; rep++) {
            if (idx < 512) {
                int h = idx >> 6, e = idx & 63;
                const float* wkp = Wk + (h * 32) * 192 + 128 + e;
                float acc = 0.f;
                #pragma unroll
                for (int a = 0; a < 32; a++) acc = fmaf(s_qi[h * 32 + a], wkp[a * 192], acc);
                s_Qk[e * 8 + h] = acc * rs;
            }
            idx += 384;
        }
    }
    if (tid < 256) {   // sim_base[h], warps 0..7
        float v = s_qi[tid] * s_Kni[tid];
        #pragma unroll
        for (int o = 16; o; o >>= 1) v += __shfl_xor_sync(0xffffffffu, v, o);
        if (lane == 0) s_sb[wid] = v * rs;
    }
    __syncthreads();

    int cnt = *s_cnt;

    // pass 1: sim for valid j only. thread = (j-slot, h-half of 4)
    {
        int hh = tid & 1;                       // 0 -> h0..3, 1 -> h4..7
        F4U sb; sb.f = *(const float4*)&s_sb[hh * 4];
        for (int idx = tid >> 1; idx < cnt; idx += 192) {
            int j = s_jl[idx];
            unsigned long long acc2[2] = { sb.u[0], sb.u[1] };
            const float* ep = Es + j;
            const float* qp = s_Qk + hh * 4;
            #pragma unroll 8
            for (int e = 0; e < 64; e++) {
                float ev = ep[e * ES_STRIDE];
                unsigned long long evd = pk2(ev, ev);
                F4U q; q.f = *(const float4*)(qp + e * 8);
                acc2[0] = fma2(q.u[0], evd, acc2[0]);
                acc2[1] = fma2(q.u[1], evd, acc2[1]);
            }
            F4U o;
            float2 a = upk(acc2[0]), b = upk(acc2[1]);
            o.f = make_float4(a.x, a.y, b.x, b.y);
            *(float4*)&s_p[j * 12 + hh * 4] = o.f;
        }
    }
    __syncthreads();

    float maski = s_mf[i];

    // masked softmax over valid j: warp h (h<8) owns head h
    if (wid < 8) {
        int h = wid;
        float m = -INFINITY;
        for (int idx = lane; idx < cnt; idx += 32) m = fmaxf(m, s_p[s_jl[idx] * 12 + h]);
        #pragma unroll
        for (int o = 16; o; o >>= 1) m = fmaxf(m, __shfl_xor_sync(0xffffffffu, m, o));
        float sum = 0.f;
        for (int idx = lane; idx < cnt; idx += 32) {
            int j = s_jl[idx];
            float ev = __expf(s_p[j * 12 + h] - m);
            s_p[j * 12 + h] = ev;
            sum += ev;
        }
        #pragma unroll
        for (int o = 16; o; o >>= 1) sum += __shfl_xor_sync(0xffffffffu, sum, o);
        float inv = maski / sum;
        for (int idx = lane; idx < cnt; idx += 32) s_p[s_jl[idx] * 12 + h] *= inv;
    }
    __syncthreads();

    // pass 2: T[h][e] = sum over valid j of p[h][j]*E[e][j]; 12 warps over e
    for (int e = wid; e < 64; e += 12) {
        const float* ep = Es + e * ES_STRIDE;
        unsigned long long acc2[4] = {0ull, 0ull, 0ull, 0ull};
        for (int idx = lane; idx < cnt; idx += 32) {
            int j = s_jl[idx];
            float ev = ep[j];
            unsigned long long evd = pk2(ev, ev);
            F4U p0; p0.f = *(const float4*)&s_p[j * 12];
            F4U p1; p1.f = *(const float4*)&s_p[j * 12 + 4];
            acc2[0] = fma2(p0.u[0], evd, acc2[0]);
            acc2[1] = fma2(p0.u[1], evd, acc2[1]);
            acc2[2] = fma2(p1.u[0], evd, acc2[2]);
            acc2[3] = fma2(p1.u[1], evd, acc2[3]);
        }
        #pragma unroll
        for (int hp = 0; hp < 4; hp++) {
            float2 v = upk(acc2[hp]);
            #pragma unroll
            for (int o = 16; o; o >>= 1) {
                v.x += __shfl_xor_sync(0xffffffffu, v.x, o);
                v.y += __shfl_xor_sync(0xffffffffu, v.y, o);
            }
            if (lane == 0) {
                s_T[(2 * hp)     * 64 + e] = v.x;
                s_T[(2 * hp + 1) * 64 + e] = v.y;
            }
        }
    }
    __syncthreads();

    // node_features[hv,i]
    if (tid < 256) {
        int hv = tid, h = hv >> 5;
        const float* wvp = Wv + hv * 192 + 128;
        float acc = s_Vni[hv] * maski;
        #pragma unroll
        for (int e = 0; e < 64; e++) acc = fmaf(wvp[e], s_T[h * 64 + e], acc);
        g_nf[hv * N + i] = acc;
    }
}

// ============================================================
// Kernel 3: node_out = Wo@nf ; hEo = 0.5*We[:,:256]@nf
// M=192, K=256, cols=384. grid(6,12), 256 thr, tile 32x32.
// ============================================================
__global__ __launch_bounds__(256) void k_post(
    const float* __restrict__ Wo,
    const float* __restrict__ We,
    float* __restrict__ out)
{
    __shared__ float Ws[32][33];
    __shared__ float Ns[32][36];
    int tid = threadIdx.x;
    int r0 = blockIdx.x * 32, n0 = blockIdx.y * 32;
    int co = tid & 31, ro = (tid >> 5) * 4;
    float acc[4] = {0.f, 0.f, 0.f, 0.f};

    for (int k0 = 0; k0 < 256; k0 += 32) {
        {
            int rr = tid >> 3, kl = (tid & 7) * 4;
            int r = r0 + rr;
            const float* wp = (r < 128) ? (Wo + r * 256) : (We + (r - 128) * 320);
            float4 w = *(const float4*)(wp + k0 + kl);
            Ws[rr][kl+0] = w.x; Ws[rr][kl+1] = w.y;
            Ws[rr][kl+2] = w.z; Ws[rr][kl+3] = w.w;
        }
        {
            int kk = tid >> 3, cl = (tid & 7) * 4;
            float4 v = *(const float4*)(g_nf + (k0 + kk) * N + n0 + cl);
            Ns[kk][cl+0] = v.x; Ns[kk][cl+1] = v.y;
            Ns[kk][cl+2] = v.z; Ns[kk][cl+3] = v.w;
        }
        __syncthreads();
        #pragma unroll
        for (int k = 0; k < 32; k++) {
            float ev = Ns[k][co];
            acc[0] = fmaf(Ws[ro+0][k], ev, acc[0]);
            acc[1] = fmaf(Ws[ro+1][k], ev, acc[1]);
            acc[2] = fmaf(Ws[ro+2][k], ev, acc[2]);
            acc[3] = fmaf(Ws[ro+3][k], ev, acc[3]);
        }
        __syncthreads();
    }
    #pragma unroll
    for (int q = 0; q < 4; q++) {
        int r = r0 + ro + q;
        if (r < 128) out[r * N + n0 + co] = acc[q];
        else         g_hEo[(r - 128) * N + n0 + co] = 0.5f * acc[q];
    }
}

// ============================================================
// Kernel 4: edge_out. GEMM [64o,64e] x [64e, 147456c] + rank-1 adds.
// grid(576), 256 thr, 2 CTAs/SM (84KB smem). CTA tile 64o x 256c.
// Thread tile 8o x 8c: c = lane*4 and lane*4+128 (conflict-free).
// FFMA2 packed along o-pairs (u64 directly from weight float4).
// ============================================================
#define EG_ST 260
#define EDGE_SMEM ((64*68 + 64*EG_ST) * 4)

__global__ __launch_bounds__(256, 2) void k_edge(
    const float* __restrict__ edges,
    const float* __restrict__ We,
    float* __restrict__ out)
{
    extern __shared__ float esm[];
    float* Ws = esm;              // [64][68]  Ws[e][o]
    float* Es = esm + 64 * 68;    // [64][260]

    int tid = threadIdx.x, lane = tid & 31, wid = tid >> 5;
    size_t cbase = (size_t)blockIdx.x * 256;

    // load We_edge transposed
    {
        int o = tid >> 2, e0 = (tid & 3) * 16;
        const float* wp = We + o * 320 + 256 + e0;
        #pragma unroll
        for (int u = 0; u < 16; u += 4) {
            float4 w = *(const float4*)(wp + u);
            Ws[(e0+u+0)*68 + o] = w.x; Ws[(e0+u+1)*68 + o] = w.y;
            Ws[(e0+u+2)*68 + o] = w.z; Ws[(e0+u+3)*68 + o] = w.w;
        }
    }
    // stage Es: 64 e x 256 c = 4096 float4 / 256 thr = 16 each
    #pragma unroll
    for (int it = 0; it < 16; it++) {
        int idx = it * 256 + tid;
        int e = idx >> 6, c4 = idx & 63;
        float4 v = *(const float4*)(edges + (size_t)e * NN + cbase + c4 * 4);
        *(float4*)&Es[e * EG_ST + c4 * 4] = v;
    }
    __syncthreads();

    int o0 = wid * 8;
    int cl = lane * 4;

    unsigned long long acc2[4][8];   // [o-pair][c]  c: 4 strip0 + 4 strip1
    #pragma unroll
    for (int op = 0; op < 4; op++)
        #pragma unroll
        for (int p = 0; p < 8; p++) acc2[op][p] = 0ull;

    #pragma unroll 4
    for (int e = 0; e < 64; e++) {
        const float* wr = Ws + e * 68 + o0;
        F4U w0; w0.f = *(const float4*)wr;
        F4U w1; w1.f = *(const float4*)(wr + 4);
        unsigned long long wd[4] = { w0.u[0], w0.u[1], w1.u[0], w1.u[1] };
        const float* er = Es + e * EG_ST + cl;
        float4 ea = *(const float4*)er;
        float4 eb = *(const float4*)(er + 128);
        float ev[8] = { ea.x, ea.y, ea.z, ea.w, eb.x, eb.y, eb.z, eb.w };
        #pragma unroll
        for (int p = 0; p < 8; p++) {
            unsigned long long evd = pk2(ev[p], ev[p]);
            acc2[0][p] = fma2(wd[0], evd, acc2[0][p]);
            acc2[1][p] = fma2(wd[1], evd, acc2[1][p]);
            acc2[2][p] = fma2(wd[2], evd, acc2[2][p]);
            acc2[3][p] = fma2(wd[3], evd, acc2[3][p]);
        }
    }

    // epilogue: add hEo[o,i] + hEo[o,j], store
    float* ob = out + 128 * N;
    #pragma unroll
    for (int s = 0; s < 2; s++) {
        size_t c = cbase + cl + s * 128;
        int ii = (int)(c / 384), jj = (int)(c % 384);
        #pragma unroll
        for (int op = 0; op < 4; op++) {
            int oA = o0 + 2 * op, oB = oA + 1;
            float eoiA = g_hEo[oA * N + ii];
            float eoiB = g_hEo[oB * N + ii];
            float4 ejA = *(const float4*)(g_hEo + oA * N + jj);
            float4 ejB = *(const float4*)(g_hEo + oB * N + jj);
            float2 v0 = upk(acc2[op][s*4+0]);
            float2 v1 = upk(acc2[op][s*4+1]);
            float2 v2 = upk(acc2[op][s*4+2]);
            float2 v3 = upk(acc2[op][s*4+3]);
            float* pA = ob + (size_t)oA * NN + c;
            float* pB = ob + (size_t)oB * NN + c;
            *(float4*)pA = make_float4(v0.x + eoiA + ejA.x, v1.x + eoiA + ejA.y,
                                       v2.x + eoiA + ejA.z, v3.x + eoiA + ejA.w);
            *(float4*)pB = make_float4(v0.y + eoiB + ejB.x, v1.y + eoiB + ejB.y,
                                       v2.y + eoiB + ejB.z, v3.y + eoiB + ejB.w);
        }
    }
}

// ============================================================
extern "C" void kernel_launch(void* const* d_in, const int* in_sizes, int n_in,
                              void* d_out, int out_size)
{
    const float* nodes = (const float*)d_in[0];
    const float* edges = (const float*)d_in[1];
    const unsigned int* mask = (const unsigned int*)d_in[2];
    const float* Wq = (const float*)d_in[3];
    const float* Wk = (const float*)d_in[4];
    const float* Wv = (const float*)d_in[5];
    const float* Wo = (const float*)d_in[6];
    const float* We = (const float*)d_in[7];
    float* out = (float*)d_out;

    cudaFuncSetAttribute(k_attn, cudaFuncAttributeMaxDynamicSharedMemorySize, ATTN_SMEM);
    cudaFuncSetAttribute(k_edge, cudaFuncAttributeMaxDynamicSharedMemorySize, EDGE_SMEM);

    k_prep<<<dim3(24, 12), 256>>>(nodes, Wq, Wk, Wv, mask);
    k_attn<<<384, 384, ATTN_SMEM>>>(edges, Wk, Wv);
    k_post<<<dim3(6, 12), 256>>>(Wo, We, out);
    k_edge<<<576, 256, EDGE_SMEM>>>(edges, We, out);
}